// round 16
// baseline (speedup 1.0000x reference)
#include <cuda_runtime.h>
#include <cstdint>

// Problem shape (fixed by setup_inputs): T=32, B=256, C_in=C_out=4096.
#define T_STEPS 32
#define BATCH   256
#define C_IN    4096
#define C_OUT   4096
#define M_DIM   (T_STEPS * BATCH)   // 8192 GEMM rows

// Scratch for pre-activation currents: [T*B, C_OUT] fp32 = 128 MB.
__device__ float g_current[(size_t)M_DIM * C_OUT];

typedef unsigned long long ull;

// Packed f32x2 ops. Per-component rounding identical to scalar RN ops.
__device__ __forceinline__ ull fma2(ull a, ull b, ull c) {
    ull d;
    asm("fma.rn.f32x2 %0, %1, %2, %3;" : "=l"(d) : "l"(a), "l"(b), "l"(c));
    return d;
}
__device__ __forceinline__ ull add2(ull a, ull b) {
    ull d;
    asm("add.rn.f32x2 %0, %1, %2;" : "=l"(d) : "l"(a), "l"(b));
    return d;
}
__device__ __forceinline__ ull pack2(float lo, float hi) {
    ull d;
    asm("mov.b64 %0, {%1, %2};" : "=l"(d) : "f"(lo), "f"(hi));
    return d;
}
__device__ __forceinline__ void unpack2(ull v, float& lo, float& hi) {
    asm("mov.b64 {%0, %1}, %2;" : "=f"(lo), "=f"(hi) : "l"(v));
}

// ---------------------------------------------------------------------------
// GEMM (NT): C[m][n] = sum_k A[m][k]*W[n][k] + bias[n]
// Per-output-element arithmetic IDENTICAL to R13/R14 (PASS @ 9.680577e-4):
// fresh 32-term packed-FMA chains per BK=32 slab (k in ascending order),
// plain add2 merge, same epilogue ops. Tile shape does not touch numerics.
// Perf change vs R14: tile 64x64 with TM=4,TN=4 shrinks the hot register
// set to ~75/thread (acc 8 ull + blk 8 ull + fragments), which fits the
// occ-3 85-reg cap WITHOUT spills -> 6 warps/SMSP to cover the slab-boundary
// latency holes that 4 warps left exposed (R14 = 93% of the rt3 floor).
// ---------------------------------------------------------------------------
#define BM 64
#define BN 64
#define BK 32
#define TM 4
#define TN 4

__global__ __launch_bounds__(256, 3)
void gemm_nt_bias_f32x2_kernel(const float* __restrict__ A,
                               const float* __restrict__ W,
                               const float* __restrict__ bias,
                               float* __restrict__ C)
{
    __shared__ float As[2][BK][BM];   // 2 x 8 KB
    __shared__ float Bs[2][BK][BN];   // 2 x 8 KB

    const int K  = C_IN;
    const int m0 = blockIdx.y * BM;
    const int n0 = blockIdx.x * BN;

    const int tid = threadIdx.x;
    const int tx  = tid & 15;      // 16 thread-cols * TN=4 -> 64
    const int ty  = tid >> 4;      // 16 thread-rows * TM=4 -> 64

    // Packed accumulators: [pair-of-m][n], pair ip covers rows (2ip, 2ip+1).
    ull acc[TM / 2][TN];
#pragma unroll
    for (int ip = 0; ip < TM / 2; ip++)
#pragma unroll
        for (int j = 0; j < TN; j++) acc[ip][j] = 0ull;

    // Register staging for global->shared prefetch.
    // A slab: 64 rows x 32 k = 512 float4 -> 2/thread. B slab: same.
    float4 rA[2], rB[2];

    auto ldg_slab = [&](int k0) {
#pragma unroll
        for (int i = 0; i < 2; i++) {
            const int s   = tid * 2 + i;
            const int row = s >> 3;       // 8 float4-chunks per row
            const int q   = s & 7;
            rA[i] = *reinterpret_cast<const float4*>(
                A + (size_t)(m0 + row) * K + k0 + q * 4);
            rB[i] = *reinterpret_cast<const float4*>(
                W + (size_t)(n0 + row) * K + k0 + q * 4);
        }
    };
    auto sts_slab = [&](int buf) {
#pragma unroll
        for (int i = 0; i < 2; i++) {
            const int s   = tid * 2 + i;
            const int row = s >> 3;
            const int q   = s & 7;
            As[buf][q * 4 + 0][row] = rA[i].x;
            As[buf][q * 4 + 1][row] = rA[i].y;
            As[buf][q * 4 + 2][row] = rA[i].z;
            As[buf][q * 4 + 3][row] = rA[i].w;
            Bs[buf][q * 4 + 0][row] = rB[i].x;
            Bs[buf][q * 4 + 1][row] = rB[i].y;
            Bs[buf][q * 4 + 2][row] = rB[i].z;
            Bs[buf][q * 4 + 3][row] = rB[i].w;
        }
    };

    // Prologue: stage slab 0.
    ldg_slab(0);
    sts_slab(0);
    __syncthreads();

    int buf = 0;
    for (int k0 = 0; k0 < K; k0 += BK) {
        const bool has_next = (k0 + BK) < K;
        if (has_next) ldg_slab(k0 + BK);   // prefetch next slab into registers

        // Fresh packed slab accumulator (32-term RN-exact FMA chains).
        ull blk[TM / 2][TN];
#pragma unroll
        for (int ip = 0; ip < TM / 2; ip++)
#pragma unroll
            for (int j = 0; j < TN; j++) blk[ip][j] = 0ull;

#pragma unroll 8
        for (int kk = 0; kk < BK; kk++) {
            // A fragment: rows ty*4 .. ty*4+3 as 2 natural f32x2 pairs
            // (one LDS.128, broadcast across tx).
            const ulonglong2 av =
                *reinterpret_cast<const ulonglong2*>(&As[buf][kk][ty * TM]);
            ull ap[2];
            ap[0] = av.x; ap[1] = av.y;

            // B fragment: 4 scalars, duplicated into packed lanes (MOVs on
            // the non-binding pipe — proven free by the R6/R12 A/B test).
            const float4 bv =
                *reinterpret_cast<const float4*>(&Bs[buf][kk][tx * TN]);
            ull bd[4];
            bd[0] = pack2(bv.x, bv.x);
            bd[1] = pack2(bv.y, bv.y);
            bd[2] = pack2(bv.z, bv.z);
            bd[3] = pack2(bv.w, bv.w);

#pragma unroll
            for (int ip = 0; ip < TM / 2; ip++)
#pragma unroll
                for (int j = 0; j < TN; j++)
                    blk[ip][j] = fma2(ap[ip], bd[j], blk[ip][j]);
        }

        // Plain merge: one packed add per accumulator per slab (irreducible).
#pragma unroll
        for (int ip = 0; ip < TM / 2; ip++)
#pragma unroll
            for (int j = 0; j < TN; j++)
                acc[ip][j] = add2(acc[ip][j], blk[ip][j]);

        if (has_next) {
            sts_slab(buf ^ 1);   // fill the idle buffer
            __syncthreads();
            buf ^= 1;
        }
    }

    // Epilogue: add bias, store fp32 currents (same exprs as R13/R14).
#pragma unroll
    for (int ip = 0; ip < TM / 2; ip++) {
        float a_lo[TN], a_hi[TN];
#pragma unroll
        for (int j = 0; j < TN; j++)
            unpack2(acc[ip][j], a_lo[j], a_hi[j]);
        const int n = n0 + tx * TN;
        {
            const int m = m0 + ty * TM + 2 * ip;
            float4 v;
            v.x = __fadd_rn(a_lo[0], bias[n + 0]);
            v.y = __fadd_rn(a_lo[1], bias[n + 1]);
            v.z = __fadd_rn(a_lo[2], bias[n + 2]);
            v.w = __fadd_rn(a_lo[3], bias[n + 3]);
            *reinterpret_cast<float4*>(C + (size_t)m * C_OUT + n) = v;
        }
        {
            const int m = m0 + ty * TM + 2 * ip + 1;
            float4 v;
            v.x = __fadd_rn(a_hi[0], bias[n + 0]);
            v.y = __fadd_rn(a_hi[1], bias[n + 1]);
            v.z = __fadd_rn(a_hi[2], bias[n + 2]);
            v.w = __fadd_rn(a_hi[3], bias[n + 3]);
            *reinterpret_cast<float4*>(C + (size_t)m * C_OUT + n) = v;
        }
    }
}

// ---------------------------------------------------------------------------
// LIF scan (identical numerics and form to the passing R5 kernel, 38.9us).
// ---------------------------------------------------------------------------
__global__ __launch_bounds__(256)
void lif_scan_kernel(const float* __restrict__ cur,
                     float* __restrict__ out,
                     const float* __restrict__ decay,
                     const float* __restrict__ thresh)
{
    const int i = blockIdx.x * blockDim.x + threadIdx.x;
    const float d  = decay[0];
    const float th = thresh[0];
    const size_t stride = (size_t)BATCH * C_OUT;

    float mem = 0.0f;
#pragma unroll
    for (int t = 0; t < T_STEPS; t++) {
        const size_t idx = (size_t)t * stride + i;
        const float c = cur[idx];
        mem = __fadd_rn(__fmul_rn(d, mem), c);
        const float v = __fsub_rn(mem, th);
        const float s = (v > 0.0f) ? 1.0f : 0.0f;
        out[idx] = s;
        mem = __fsub_rn(mem, __fmul_rn(s, th));
    }
}

// ---------------------------------------------------------------------------
// Launch: inputs in metadata order: x, W, b, decay, thresh.
// ---------------------------------------------------------------------------
extern "C" void kernel_launch(void* const* d_in, const int* in_sizes, int n_in,
                              void* d_out, int out_size)
{
    const float* x      = (const float*)d_in[0];  // [T, B, C_IN]
    const float* W      = (const float*)d_in[1];  // [C_OUT, C_IN]
    const float* bias   = (const float*)d_in[2];  // [C_OUT]
    const float* decay  = (const float*)d_in[3];  // [1]
    const float* thresh = (const float*)d_in[4];  // [1]
    float* out = (float*)d_out;                   // [T, B, C_OUT]

    float* cur = nullptr;
    cudaGetSymbolAddress((void**)&cur, g_current);

    dim3 gblock(256);
    dim3 ggrid(C_OUT / BN, M_DIM / BM);   // (64, 128)
    gemm_nt_bias_f32x2_kernel<<<ggrid, gblock>>>(x, W, bias, cur);

    const int neurons = BATCH * C_OUT;    // 1,048,576
    lif_scan_kernel<<<neurons / 256, 256>>>(cur, out, decay, thresh);
}

// round 17
// speedup vs baseline: 1.2679x; 1.2679x over previous
#include <cuda_runtime.h>
#include <cstdint>

// Problem shape (fixed by setup_inputs): T=32, B=256, C_in=C_out=4096.
#define T_STEPS 32
#define BATCH   256
#define C_IN    4096
#define C_OUT   4096
#define M_DIM   (T_STEPS * BATCH)   // 8192 GEMM rows

// Scratch for pre-activation currents: [T*B, C_OUT] fp32 = 128 MB.
__device__ float g_current[(size_t)M_DIM * C_OUT];

typedef unsigned long long ull;

// Packed f32x2 ops. Per-component rounding identical to scalar RN ops.
__device__ __forceinline__ ull fma2(ull a, ull b, ull c) {
    ull d;
    asm("fma.rn.f32x2 %0, %1, %2, %3;" : "=l"(d) : "l"(a), "l"(b), "l"(c));
    return d;
}
__device__ __forceinline__ ull add2(ull a, ull b) {
    ull d;
    asm("add.rn.f32x2 %0, %1, %2;" : "=l"(d) : "l"(a), "l"(b));
    return d;
}
__device__ __forceinline__ ull pack2(float lo, float hi) {
    ull d;
    asm("mov.b64 %0, {%1, %2};" : "=l"(d) : "f"(lo), "f"(hi));
    return d;
}
__device__ __forceinline__ void unpack2(ull v, float& lo, float& hi) {
    asm("mov.b64 {%0, %1}, %2;" : "=f"(lo), "=f"(hi) : "l"(v));
}

// ---------------------------------------------------------------------------
// GEMM (NT): C[m][n] = sum_k A[m][k]*W[n][k] + bias[n]
// EXACTLY the R14 configuration (6096us PASS @ 9.680577e-4): BM128/BN64/BK32,
// TM8/TN4, occ-2, unroll 8, fresh 32-term packed-FMA chains per slab, plain
// add2 merge. The ONLY change is instruction scheduling: the STS of the
// prefetched next slab is hoisted between the two 16-kk compute halves, so
// its issue cost and drain hide under the FFMA2 stream instead of sitting in
// the serial boundary window (compute -> STS -> bar -> LDS refill).
// Per-output-element arithmetic is byte-identical to R14.
// ---------------------------------------------------------------------------
#define BM 128
#define BN 64
#define BK 32
#define TM 8
#define TN 4

__global__ __launch_bounds__(256, 2)
void gemm_nt_bias_f32x2_kernel(const float* __restrict__ A,
                               const float* __restrict__ W,
                               const float* __restrict__ bias,
                               float* __restrict__ C)
{
    __shared__ float As[2][BK][BM];   // 2 x 16 KB
    __shared__ float Bs[2][BK][BN];   // 2 x  8 KB

    const int K  = C_IN;
    const int m0 = blockIdx.y * BM;
    const int n0 = blockIdx.x * BN;

    const int tid = threadIdx.x;
    const int tx  = tid & 15;      // 16 thread-cols * TN=4  -> 64
    const int ty  = tid >> 4;      // 16 thread-rows * TM=8  -> 128

    // Packed accumulators: [pair-of-m][n], pair ip covers rows (2ip, 2ip+1).
    ull acc[TM / 2][TN];
#pragma unroll
    for (int ip = 0; ip < TM / 2; ip++)
#pragma unroll
        for (int j = 0; j < TN; j++) acc[ip][j] = 0ull;

    // Register staging for global->shared prefetch (same slot plan as R14).
    float4 rA[4], rB[2];

    auto ldg_slab = [&](int k0) {
#pragma unroll
        for (int i = 0; i < 4; i++) {
            const int s   = tid * 4 + i;
            const int row = s >> 3;
            const int q   = s & 7;
            rA[i] = *reinterpret_cast<const float4*>(
                A + (size_t)(m0 + row) * K + k0 + q * 4);
        }
#pragma unroll
        for (int i = 0; i < 2; i++) {
            const int s   = tid * 2 + i;
            const int row = s >> 3;
            const int q   = s & 7;
            rB[i] = *reinterpret_cast<const float4*>(
                W + (size_t)(n0 + row) * K + k0 + q * 4);
        }
    };
    auto sts_slab = [&](int buf) {
#pragma unroll
        for (int i = 0; i < 4; i++) {
            const int s   = tid * 4 + i;
            const int row = s >> 3;
            const int q   = s & 7;
            As[buf][q * 4 + 0][row] = rA[i].x;
            As[buf][q * 4 + 1][row] = rA[i].y;
            As[buf][q * 4 + 2][row] = rA[i].z;
            As[buf][q * 4 + 3][row] = rA[i].w;
        }
#pragma unroll
        for (int i = 0; i < 2; i++) {
            const int s   = tid * 2 + i;
            const int row = s >> 3;
            const int q   = s & 7;
            Bs[buf][q * 4 + 0][row] = rB[i].x;
            Bs[buf][q * 4 + 1][row] = rB[i].y;
            Bs[buf][q * 4 + 2][row] = rB[i].z;
            Bs[buf][q * 4 + 3][row] = rB[i].w;
        }
    };

    // One 16-step compute half (arithmetic order identical to R14's loop).
    auto compute_half = [&](int buf, int kbase, ull blk[TM / 2][TN]) {
#pragma unroll 8
        for (int kk2 = 0; kk2 < BK / 2; kk2++) {
            const int kk = kbase + kk2;
            const ulonglong2 av0 =
                *reinterpret_cast<const ulonglong2*>(&As[buf][kk][ty * TM]);
            const ulonglong2 av1 =
                *reinterpret_cast<const ulonglong2*>(&As[buf][kk][ty * TM + 4]);
            ull ap[4];
            ap[0] = av0.x; ap[1] = av0.y; ap[2] = av1.x; ap[3] = av1.y;

            const float4 bv =
                *reinterpret_cast<const float4*>(&Bs[buf][kk][tx * TN]);
            ull bd[4];
            bd[0] = pack2(bv.x, bv.x);
            bd[1] = pack2(bv.y, bv.y);
            bd[2] = pack2(bv.z, bv.z);
            bd[3] = pack2(bv.w, bv.w);

#pragma unroll
            for (int ip = 0; ip < TM / 2; ip++)
#pragma unroll
                for (int j = 0; j < TN; j++)
                    blk[ip][j] = fma2(ap[ip], bd[j], blk[ip][j]);
        }
    };

    // Prologue: stage slab 0.
    ldg_slab(0);
    sts_slab(0);
    __syncthreads();

    int buf = 0;
    for (int k0 = 0; k0 < K; k0 += BK) {
        const bool has_next = (k0 + BK) < K;
        if (has_next) ldg_slab(k0 + BK);   // prefetch next slab into registers

        // Fresh packed slab accumulator (32-term RN-exact FMA chains).
        ull blk[TM / 2][TN];
#pragma unroll
        for (int ip = 0; ip < TM / 2; ip++)
#pragma unroll
            for (int j = 0; j < TN; j++) blk[ip][j] = 0ull;

        // First half of the slab (kk = 0..15).
        compute_half(buf, 0, blk);

        // Hoisted STS: the prefetch LDG has completed by now (~600cyc lat vs
        // ~2300cyc of compute); buffer buf^1 is dead since the previous
        // barrier. Issues on the LSU pipe under the second half's FFMA2s.
        if (has_next) sts_slab(buf ^ 1);

        // Second half of the slab (kk = 16..31).
        compute_half(buf, BK / 2, blk);

        // Plain merge: one packed add per accumulator per slab (irreducible).
#pragma unroll
        for (int ip = 0; ip < TM / 2; ip++)
#pragma unroll
            for (int j = 0; j < TN; j++)
                acc[ip][j] = add2(acc[ip][j], blk[ip][j]);

        if (has_next) {
            __syncthreads();   // STS to buf^1 visible to all before reading
            buf ^= 1;
        }
    }

    // Epilogue: add bias, store fp32 currents (same exprs as R13/R14).
#pragma unroll
    for (int ip = 0; ip < TM / 2; ip++) {
        float a_lo[TN], a_hi[TN];
#pragma unroll
        for (int j = 0; j < TN; j++)
            unpack2(acc[ip][j], a_lo[j], a_hi[j]);
        const int n = n0 + tx * TN;
        {
            const int m = m0 + ty * TM + 2 * ip;
            float4 v;
            v.x = __fadd_rn(a_lo[0], bias[n + 0]);
            v.y = __fadd_rn(a_lo[1], bias[n + 1]);
            v.z = __fadd_rn(a_lo[2], bias[n + 2]);
            v.w = __fadd_rn(a_lo[3], bias[n + 3]);
            *reinterpret_cast<float4*>(C + (size_t)m * C_OUT + n) = v;
        }
        {
            const int m = m0 + ty * TM + 2 * ip + 1;
            float4 v;
            v.x = __fadd_rn(a_hi[0], bias[n + 0]);
            v.y = __fadd_rn(a_hi[1], bias[n + 1]);
            v.z = __fadd_rn(a_hi[2], bias[n + 2]);
            v.w = __fadd_rn(a_hi[3], bias[n + 3]);
            *reinterpret_cast<float4*>(C + (size_t)m * C_OUT + n) = v;
        }
    }
}

// ---------------------------------------------------------------------------
// LIF scan (identical numerics and form to the passing R5 kernel, 38.9us).
// ---------------------------------------------------------------------------
__global__ __launch_bounds__(256)
void lif_scan_kernel(const float* __restrict__ cur,
                     float* __restrict__ out,
                     const float* __restrict__ decay,
                     const float* __restrict__ thresh)
{
    const int i = blockIdx.x * blockDim.x + threadIdx.x;
    const float d  = decay[0];
    const float th = thresh[0];
    const size_t stride = (size_t)BATCH * C_OUT;

    float mem = 0.0f;
#pragma unroll
    for (int t = 0; t < T_STEPS; t++) {
        const size_t idx = (size_t)t * stride + i;
        const float c = cur[idx];
        mem = __fadd_rn(__fmul_rn(d, mem), c);
        const float v = __fsub_rn(mem, th);
        const float s = (v > 0.0f) ? 1.0f : 0.0f;
        out[idx] = s;
        mem = __fsub_rn(mem, __fmul_rn(s, th));
    }
}

// ---------------------------------------------------------------------------
// Launch: inputs in metadata order: x, W, b, decay, thresh.
// ---------------------------------------------------------------------------
extern "C" void kernel_launch(void* const* d_in, const int* in_sizes, int n_in,
                              void* d_out, int out_size)
{
    const float* x      = (const float*)d_in[0];  // [T, B, C_IN]
    const float* W      = (const float*)d_in[1];  // [C_OUT, C_IN]
    const float* bias   = (const float*)d_in[2];  // [C_OUT]
    const float* decay  = (const float*)d_in[3];  // [1]
    const float* thresh = (const float*)d_in[4];  // [1]
    float* out = (float*)d_out;                   // [T, B, C_OUT]

    float* cur = nullptr;
    cudaGetSymbolAddress((void**)&cur, g_current);

    dim3 gblock(256);
    dim3 ggrid(C_OUT / BN, M_DIM / BM);   // (64, 64)
    gemm_nt_bias_f32x2_kernel<<<ggrid, gblock>>>(x, W, bias, cur);

    const int neurons = BATCH * C_OUT;    // 1,048,576
    lif_scan_kernel<<<neurons / 256, 256>>>(cur, out, decay, thresh);
}